// round 3
// baseline (speedup 1.0000x reference)
#include <cuda_runtime.h>
#include <cstddef>

#define N_NODES 50000
#define NE      640000
#define ET      (NE + N_NODES)   // edges + self loops = 690000
#define D_IN    128
#define HID     64
#define HEADS   3
#define SLOPE   0.2f
#define EPS     1e-16f

// ---------------- scratch (no allocations; referenced ONLY from device code) ----------------
__device__ float g_xw[(size_t)N_NODES * HEADS * HID];   // xw1 then reused as xw2
__device__ float g_h1[(size_t)N_NODES * HEADS * HID];   // layer-1 output
__device__ float g_asrc[N_NODES * HEADS];
__device__ float g_adst[N_NODES * HEADS];
__device__ float g_ex[(size_t)ET * HEADS];              // exp(logit) per CSR slot
__device__ int   g_counts[N_NODES];
__device__ int   g_offsets[N_NODES + 1];
__device__ int   g_cursor[N_NODES];
__device__ int   g_csr_src[ET];
__device__ int   g_csr_dst[ET];
__device__ int   g_is64;

// ---------------- edge-index dtype probe ----------------
// If edge_index is int64 (values < 2^31, little-endian), every odd 32-bit word
// of the buffer is 0. If it's int32, odd words are random node ids (OR != 0).
__global__ void probe_kernel(const int* __restrict__ ei32) {
    __shared__ int s_or[256];
    int tid = threadIdx.x;
    int acc = 0;
    // look at odd words of the first 4096 int32 slots
    for (int i = tid; i < 2048; i += 256) acc |= ei32[2 * i + 1];
    s_or[tid] = acc;
    __syncthreads();
    for (int s = 128; s > 0; s >>= 1) {
        if (tid < s) s_or[tid] |= s_or[tid + s];
        __syncthreads();
    }
    if (tid == 0) g_is64 = (s_or[0] == 0) ? 1 : 0;
}

__device__ __forceinline__ int edge_at(const void* ei, long long idx) {
    if (g_is64) return (int)((const long long*)ei)[idx];
    return ((const int*)ei)[idx];
}

// ---------------- CSR build ----------------
__global__ void zero_counts_kernel() {
    int i = blockIdx.x * blockDim.x + threadIdx.x;
    if (i < N_NODES) g_counts[i] = 0;
}

__global__ void copy_cursor_kernel() {
    int i = blockIdx.x * blockDim.x + threadIdx.x;
    if (i < N_NODES) g_cursor[i] = g_offsets[i];
}

__global__ void count_kernel(const void* __restrict__ ei) {
    int e = blockIdx.x * blockDim.x + threadIdx.x;
    if (e >= ET) return;
    int dst = (e < NE) ? edge_at(ei, (long long)NE + e) : (e - NE);
    atomicAdd(&g_counts[dst], 1);
}

// single-block scan over 50000 counts -> exclusive offsets (+ total at [N_NODES])
__global__ void scan_kernel() {
    __shared__ int warp_sums[32];
    __shared__ int s_carry;
    int tid = threadIdx.x, lane = tid & 31, wid = tid >> 5;
    if (tid == 0) s_carry = 0;
    __syncthreads();
    for (int base = 0; base < N_NODES; base += 1024) {
        int idx = base + tid;
        int v = (idx < N_NODES) ? g_counts[idx] : 0;
        int x = v;
        #pragma unroll
        for (int o = 1; o < 32; o <<= 1) {
            int y = __shfl_up_sync(0xffffffffu, x, o);
            if (lane >= o) x += y;
        }
        if (lane == 31) warp_sums[wid] = x;
        __syncthreads();
        if (wid == 0) {
            int w = warp_sums[lane];
            #pragma unroll
            for (int o = 1; o < 32; o <<= 1) {
                int y = __shfl_up_sync(0xffffffffu, w, o);
                if (lane >= o) w += y;
            }
            warp_sums[lane] = w;
        }
        __syncthreads();
        int warp_off = (wid > 0) ? warp_sums[wid - 1] : 0;
        int incl = x + warp_off;
        int excl = incl - v + s_carry;
        if (idx < N_NODES) g_offsets[idx] = excl;
        __syncthreads();
        if (tid == 1023) s_carry += incl;
        __syncthreads();
    }
    if (tid == 0) g_offsets[N_NODES] = s_carry;
}

__global__ void scatter_kernel(const void* __restrict__ ei) {
    int e = blockIdx.x * blockDim.x + threadIdx.x;
    if (e >= ET) return;
    int src, dst;
    if (e < NE) {
        src = edge_at(ei, e);
        dst = edge_at(ei, (long long)NE + e);
    } else {
        src = e - NE; dst = e - NE;
    }
    int pos = atomicAdd(&g_cursor[dst], 1);
    g_csr_src[pos] = src;
    g_csr_dst[pos] = dst;
}

// ---------------- SGEMM: C[M,N] = A[M,K] @ B[K,N], C = g_xw ----------------
// BM=64, BN=64, BK=16, 256 threads, 4x4 per thread. N,K multiples of 16.
// A_in == nullptr means A = g_h1 (layer 2).
__global__ __launch_bounds__(256)
void sgemm64_kernel(const float* __restrict__ A_in, const float* __restrict__ B,
                    int M, int N, int K) {
    const float* A = A_in ? A_in : (const float*)g_h1;
    __shared__ float As[16][64];
    __shared__ float Bs[16][64];
    int tid = threadIdx.x;
    int tx = tid & 15, ty = tid >> 4;
    int m0 = blockIdx.x * 64, n0 = blockIdx.y * 64;
    int arow = tid >> 2;           // 0..63
    int acol = (tid & 3) * 4;      // 0,4,8,12
    int brow = tid >> 4;           // 0..15
    int bcol = (tid & 15) * 4;     // 0..60
    float acc[4][4] = {};
    for (int k0 = 0; k0 < K; k0 += 16) {
        float4 av = make_float4(0.f, 0.f, 0.f, 0.f);
        if (m0 + arow < M)
            av = *(const float4*)(A + (size_t)(m0 + arow) * K + k0 + acol);
        As[acol + 0][arow] = av.x;
        As[acol + 1][arow] = av.y;
        As[acol + 2][arow] = av.z;
        As[acol + 3][arow] = av.w;
        float4 bv = *(const float4*)(B + (size_t)(k0 + brow) * N + n0 + bcol);
        *(float4*)&Bs[brow][bcol] = bv;
        __syncthreads();
        #pragma unroll
        for (int k = 0; k < 16; k++) {
            float ra[4], rb[4];
            #pragma unroll
            for (int i = 0; i < 4; i++) ra[i] = As[k][ty * 4 + i];
            #pragma unroll
            for (int j = 0; j < 4; j++) rb[j] = Bs[k][tx * 4 + j];
            #pragma unroll
            for (int i = 0; i < 4; i++)
                #pragma unroll
                for (int j = 0; j < 4; j++) acc[i][j] += ra[i] * rb[j];
        }
        __syncthreads();
    }
    #pragma unroll
    for (int i = 0; i < 4; i++) {
        int m = m0 + ty * 4 + i;
        if (m < M) {
            #pragma unroll
            for (int j = 0; j < 4; j++)
                g_xw[(size_t)m * N + n0 + tx * 4 + j] = acc[i][j];
        }
    }
}

// ---------------- per-node attention coefficients (a_src, a_dst dots) ----------------
// one warp per (node, head); 64 channels; reads g_xw, writes g_asrc/g_adst
__global__ void alpha_kernel(const float* __restrict__ a_src,
                             const float* __restrict__ a_dst, int H) {
    int warp = (blockIdx.x * blockDim.x + threadIdx.x) >> 5;
    int lane = threadIdx.x & 31;
    if (warp >= N_NODES * H) return;
    int n = warp / H, h = warp % H;
    const float* row = g_xw + (size_t)n * H * HID + h * HID;
    const float* asv = a_src + h * HID;
    const float* adv = a_dst + h * HID;
    float s1 = row[lane] * asv[lane] + row[lane + 32] * asv[lane + 32];
    float s2 = row[lane] * adv[lane] + row[lane + 32] * adv[lane + 32];
    #pragma unroll
    for (int o = 16; o > 0; o >>= 1) {
        s1 += __shfl_xor_sync(0xffffffffu, s1, o);
        s2 += __shfl_xor_sync(0xffffffffu, s2, o);
    }
    if (lane == 0) {
        g_asrc[n * H + h] = s1;
        g_adst[n * H + h] = s2;
    }
}

// ---------------- per-edge exp(leaky_relu(logit)) ----------------
// Softmax max-subtraction skipped: exp(l)/sum(exp(l)) is identical and logits
// are bounded (|l| <~ 10) so no overflow risk.
__global__ void coef_kernel(int H) {
    int i = blockIdx.x * blockDim.x + threadIdx.x;
    if (i >= ET) return;
    int src = g_csr_src[i];
    int dst = g_csr_dst[i];
    for (int h = 0; h < H; h++) {
        float v = g_asrc[src * H + h] + g_adst[dst * H + h];
        v = (v > 0.f) ? v : SLOPE * v;
        g_ex[(size_t)i * H + h] = __expf(v);
    }
}

// ---------------- per-node aggregation: out[n] = relu(sum ex*xw[src]/denom + bias) ----------------
// out_p == nullptr -> write g_h1 (layer 1)
template <int H, int C>
__global__ void aggregate_kernel(const float* __restrict__ bias,
                                 float* __restrict__ out_p) {
    float* out = out_p ? out_p : (float*)g_h1;
    int n = blockIdx.x;
    int tid = threadIdx.x;           // H*C threads
    int h = tid / C;
    int c = tid % C;
    int beg = g_offsets[n], end = g_offsets[n + 1];
    __shared__ int   s_src[32];
    __shared__ float s_ex[32 * H];
    float acc = 0.f, denom = 0.f;
    for (int base = beg; base < end; base += 32) {
        int ne = min(32, end - base);
        __syncthreads();
        if (tid < ne) s_src[tid] = g_csr_src[base + tid];
        if (tid < ne * H) s_ex[tid] = g_ex[(size_t)base * H + tid];
        __syncthreads();
        for (int j = 0; j < ne; j++) {
            float e = s_ex[j * H + h];
            denom += e;
            acc += e * g_xw[(size_t)s_src[j] * (H * C) + h * C + c];
        }
    }
    float r = acc / (denom + EPS) + bias[tid];
    out[(size_t)n * (H * C) + tid] = fmaxf(r, 0.f);
}

// ---------------- launch ----------------
extern "C" void kernel_launch(void* const* d_in, const int* in_sizes, int n_in,
                              void* d_out, int out_size) {
    const float* x   = (const float*)d_in[0];
    const void*  ei  = d_in[1];                 // int32 or int64 (probed on device)
    const float* W1  = (const float*)d_in[2];
    const float* as1 = (const float*)d_in[3];
    const float* ad1 = (const float*)d_in[4];
    const float* b1  = (const float*)d_in[5];
    const float* W2  = (const float*)d_in[6];
    const float* as2 = (const float*)d_in[7];
    const float* ad2 = (const float*)d_in[8];
    const float* b2  = (const float*)d_in[9];
    float*       out = (float*)d_out;

    const int TB = 256;
    int gridN = (N_NODES + TB - 1) / TB;
    int gridE = (ET + TB - 1) / TB;

    // --- dtype probe + CSR by destination (shared by both layers) ---
    probe_kernel<<<1, 256>>>((const int*)ei);
    zero_counts_kernel<<<gridN, TB>>>();
    count_kernel<<<gridE, TB>>>(ei);
    scan_kernel<<<1, 1024>>>();
    copy_cursor_kernel<<<gridN, TB>>>();
    scatter_kernel<<<gridE, TB>>>(ei);

    // --- layer 1: H=3, C=64 ---
    {
        dim3 g((N_NODES + 63) / 64, (HEADS * HID) / 64);
        sgemm64_kernel<<<g, 256>>>(x, W1, N_NODES, HEADS * HID, D_IN);
    }
    alpha_kernel<<<(N_NODES * HEADS + 7) / 8, 256>>>(as1, ad1, HEADS);
    coef_kernel<<<gridE, TB>>>(HEADS);
    aggregate_kernel<HEADS, HID><<<N_NODES, HEADS * HID>>>(b1, nullptr);

    // --- layer 2: H=1, C=64 (g_xw reused) ---
    {
        dim3 g((N_NODES + 63) / 64, HID / 64);
        sgemm64_kernel<<<g, 256>>>(nullptr, W2, N_NODES, HID, HEADS * HID);
    }
    alpha_kernel<<<(N_NODES + 7) / 8, 256>>>(as2, ad2, 1);
    coef_kernel<<<gridE, TB>>>(1);
    aggregate_kernel<1, HID><<<N_NODES, HID>>>(b2, out);
}

// round 4
// speedup vs baseline: 1.1675x; 1.1675x over previous
#include <cuda_runtime.h>
#include <cstddef>

#define N_NODES 50000
#define NE      640000
#define ET      (NE + N_NODES)   // edges + self loops = 690000
#define D_IN    128
#define HID     64
#define HEADS   3
#define SLOPE   0.2f
#define EPS     1e-16f

#define SCAN_BLK 1024
#define NBLK     ((N_NODES + SCAN_BLK - 1) / SCAN_BLK)   // 49

// ---------------- scratch (no allocations; referenced ONLY from device code) ----------------
__device__ float g_xw[(size_t)N_NODES * HEADS * HID];   // xw1 then reused as xw2
__device__ float g_h1[(size_t)N_NODES * HEADS * HID];   // layer-1 output
__device__ float g_asrc[N_NODES * HEADS];
__device__ float g_adst[N_NODES * HEADS];
__device__ int   g_counts[N_NODES];
__device__ int   g_offsets[N_NODES + 1];
__device__ int   g_cursor[N_NODES];
__device__ int   g_csr_src[ET];
__device__ int   g_blocksums[NBLK];
__device__ int   g_blockbase[NBLK];
__device__ int   g_is64;

// ---------------- edge-index dtype probe ----------------
// int64 (<2^31, LE): every odd 32-bit word is 0. int32: odd words are random ids.
__global__ void probe_kernel(const int* __restrict__ ei32) {
    __shared__ int s_or[256];
    int tid = threadIdx.x;
    int acc = 0;
    for (int i = tid; i < 2048; i += 256) acc |= ei32[2 * i + 1];
    s_or[tid] = acc;
    __syncthreads();
    for (int s = 128; s > 0; s >>= 1) {
        if (tid < s) s_or[tid] |= s_or[tid + s];
        __syncthreads();
    }
    if (tid == 0) g_is64 = (s_or[0] == 0) ? 1 : 0;
}

__device__ __forceinline__ int edge_at(const void* ei, long long idx) {
    if (g_is64) return (int)((const long long*)ei)[idx];
    return ((const int*)ei)[idx];
}

// ---------------- CSR build ----------------
__global__ void zero_counts_kernel() {
    int i = blockIdx.x * blockDim.x + threadIdx.x;
    if (i < N_NODES) g_counts[i] = 0;
}

__global__ void count_kernel(const void* __restrict__ ei) {
    int e = blockIdx.x * blockDim.x + threadIdx.x;
    if (e >= ET) return;
    int dst = (e < NE) ? edge_at(ei, (long long)NE + e) : (e - NE);
    atomicAdd(&g_counts[dst], 1);
}

// multi-block scan, stage 1: per-block exclusive scan + block total
__global__ void scan_part_kernel() {
    __shared__ int warp_sums[32];
    int tid = threadIdx.x, lane = tid & 31, wid = tid >> 5;
    int idx = blockIdx.x * SCAN_BLK + tid;
    int v = (idx < N_NODES) ? g_counts[idx] : 0;
    int x = v;
    #pragma unroll
    for (int o = 1; o < 32; o <<= 1) {
        int y = __shfl_up_sync(0xffffffffu, x, o);
        if (lane >= o) x += y;
    }
    if (lane == 31) warp_sums[wid] = x;
    __syncthreads();
    if (wid == 0) {
        int w = warp_sums[lane];
        #pragma unroll
        for (int o = 1; o < 32; o <<= 1) {
            int y = __shfl_up_sync(0xffffffffu, w, o);
            if (lane >= o) w += y;
        }
        warp_sums[lane] = w;
    }
    __syncthreads();
    int warp_off = (wid > 0) ? warp_sums[wid - 1] : 0;
    int incl = x + warp_off;
    if (idx < N_NODES) g_offsets[idx] = incl - v;   // local exclusive
    if (tid == SCAN_BLK - 1) g_blocksums[blockIdx.x] = incl;
}

// stage 2: scan NBLK block sums (single warp-ish block)
__global__ void scan_sums_kernel() {
    int tid = threadIdx.x;                 // 64 threads
    __shared__ int s[NBLK];
    if (tid < NBLK) s[tid] = g_blocksums[tid];
    __syncthreads();
    if (tid == 0) {
        int run = 0;
        for (int i = 0; i < NBLK; i++) { g_blockbase[i] = run; run += s[i]; }
        g_offsets[N_NODES] = run;
    }
}

// stage 3: add block bases
__global__ void scan_fixup_kernel() {
    int idx = blockIdx.x * SCAN_BLK + threadIdx.x;
    if (idx < N_NODES) g_offsets[idx] += g_blockbase[blockIdx.x];
}

__global__ void copy_cursor_kernel() {
    int i = blockIdx.x * blockDim.x + threadIdx.x;
    if (i < N_NODES) g_cursor[i] = g_offsets[i];
}

__global__ void scatter_kernel(const void* __restrict__ ei) {
    int e = blockIdx.x * blockDim.x + threadIdx.x;
    if (e >= ET) return;
    int src, dst;
    if (e < NE) {
        src = edge_at(ei, e);
        dst = edge_at(ei, (long long)NE + e);
    } else {
        src = e - NE; dst = e - NE;
    }
    int pos = atomicAdd(&g_cursor[dst], 1);
    g_csr_src[pos] = src;
}

// ---------------- SGEMM: g_xw[M,N] = A[M,K] @ B[K,N] ----------------
// BM=128, BN=64, BK=16, 256 threads, 8x4 per thread. N,K multiples of 16.
// A_in == nullptr means A = g_h1 (layer 2).
__global__ __launch_bounds__(256)
void sgemm128_kernel(const float* __restrict__ A_in, const float* __restrict__ B,
                     int M, int N, int K) {
    const float* A = A_in ? A_in : (const float*)g_h1;
    __shared__ float As[16][128];
    __shared__ float Bs[16][64];
    int tid = threadIdx.x;
    int tx = tid & 15, ty = tid >> 4;          // tx: col group (4 cols), ty: row group (8 rows)
    int m0 = blockIdx.x * 128, n0 = blockIdx.y * 64;
    int arow = tid >> 1;                       // 0..127
    int acol = (tid & 1) * 8;                  // 0 or 8
    int brow = tid >> 4;                       // 0..15
    int bcol = (tid & 15) * 4;                 // 0..60
    float acc[8][4] = {};
    for (int k0 = 0; k0 < K; k0 += 16) {
        float4 a0 = make_float4(0.f, 0.f, 0.f, 0.f);
        float4 a1 = a0;
        if (m0 + arow < M) {
            const float* ap = A + (size_t)(m0 + arow) * K + k0 + acol;
            a0 = *(const float4*)ap;
            a1 = *(const float4*)(ap + 4);
        }
        As[acol + 0][arow] = a0.x; As[acol + 1][arow] = a0.y;
        As[acol + 2][arow] = a0.z; As[acol + 3][arow] = a0.w;
        As[acol + 4][arow] = a1.x; As[acol + 5][arow] = a1.y;
        As[acol + 6][arow] = a1.z; As[acol + 7][arow] = a1.w;
        *(float4*)&Bs[brow][bcol] =
            *(const float4*)(B + (size_t)(k0 + brow) * N + n0 + bcol);
        __syncthreads();
        #pragma unroll
        for (int k = 0; k < 16; k++) {
            float4 ra0 = *(float4*)&As[k][ty * 8];
            float4 ra1 = *(float4*)&As[k][ty * 8 + 4];
            float4 rb  = *(float4*)&Bs[k][tx * 4];
            float ra[8] = {ra0.x, ra0.y, ra0.z, ra0.w, ra1.x, ra1.y, ra1.z, ra1.w};
            float rbv[4] = {rb.x, rb.y, rb.z, rb.w};
            #pragma unroll
            for (int i = 0; i < 8; i++)
                #pragma unroll
                for (int j = 0; j < 4; j++) acc[i][j] += ra[i] * rbv[j];
        }
        __syncthreads();
    }
    #pragma unroll
    for (int i = 0; i < 8; i++) {
        int m = m0 + ty * 8 + i;
        if (m < M) {
            float4 v = make_float4(acc[i][0], acc[i][1], acc[i][2], acc[i][3]);
            *(float4*)&g_xw[(size_t)m * N + n0 + tx * 4] = v;
        }
    }
}

// ---------------- per-node attention coefficients (a_src, a_dst dots) ----------------
__global__ void alpha_kernel(const float* __restrict__ a_src,
                             const float* __restrict__ a_dst, int H) {
    int warp = (blockIdx.x * blockDim.x + threadIdx.x) >> 5;
    int lane = threadIdx.x & 31;
    if (warp >= N_NODES * H) return;
    int n = warp / H, h = warp % H;
    const float* row = g_xw + (size_t)n * H * HID + h * HID;
    const float* asv = a_src + h * HID;
    const float* adv = a_dst + h * HID;
    float s1 = row[lane] * asv[lane] + row[lane + 32] * asv[lane + 32];
    float s2 = row[lane] * adv[lane] + row[lane + 32] * adv[lane + 32];
    #pragma unroll
    for (int o = 16; o > 0; o >>= 1) {
        s1 += __shfl_xor_sync(0xffffffffu, s1, o);
        s2 += __shfl_xor_sync(0xffffffffu, s2, o);
    }
    if (lane == 0) {
        g_asrc[n * H + h] = s1;
        g_adst[n * H + h] = s2;
    }
}

// ---------------- fused per-node softmax + aggregation ----------------
// out[n] = relu(sum_e ex_e * xw[src_e] / sum_e ex_e + bias)
// ex computed in-kernel: exp(leaky_relu(asrc[src] + adst[n])). Max-subtraction
// skipped (mathematically identical; logits bounded, no overflow).
// out_p == nullptr -> write g_h1 (layer 1)
template <int H, int C>
__global__ void aggregate_kernel(const float* __restrict__ bias,
                                 float* __restrict__ out_p) {
    constexpr int CHUNK = 64;
    float* out = out_p ? out_p : (float*)g_h1;
    int n = blockIdx.x;
    int tid = threadIdx.x;            // H*C threads (192 or 64)
    int h = tid / C;
    int c = tid % C;
    int beg = g_offsets[n], end = g_offsets[n + 1];
    __shared__ int   s_src[CHUNK];
    __shared__ float s_ex[CHUNK * H];
    float adst_n = g_adst[n * H + h];
    float acc = 0.f, denom = 0.f;
    for (int base = beg; base < end; base += CHUNK) {
        int ne = min(CHUNK, end - base);
        __syncthreads();
        if (tid < ne) s_src[tid] = g_csr_src[base + tid];
        __syncthreads();
        if (tid < ne * H) {
            int j = tid / H, hh = tid % H;
            float v = g_asrc[s_src[j] * H + hh] + g_adst[n * H + hh];
            v = (v > 0.f) ? v : SLOPE * v;
            s_ex[tid] = __expf(v);
        }
        __syncthreads();
        for (int j = 0; j < ne; j++) {
            float e = s_ex[j * H + h];
            denom += e;
            acc += e * g_xw[(size_t)s_src[j] * (H * C) + h * C + c];
        }
    }
    (void)adst_n;
    float r = acc / (denom + EPS) + bias[tid];
    out[(size_t)n * (H * C) + tid] = fmaxf(r, 0.f);
}

// ---------------- launch ----------------
extern "C" void kernel_launch(void* const* d_in, const int* in_sizes, int n_in,
                              void* d_out, int out_size) {
    const float* x   = (const float*)d_in[0];
    const void*  ei  = d_in[1];                 // int32 or int64 (probed on device)
    const float* W1  = (const float*)d_in[2];
    const float* as1 = (const float*)d_in[3];
    const float* ad1 = (const float*)d_in[4];
    const float* b1  = (const float*)d_in[5];
    const float* W2  = (const float*)d_in[6];
    const float* as2 = (const float*)d_in[7];
    const float* ad2 = (const float*)d_in[8];
    const float* b2  = (const float*)d_in[9];
    float*       out = (float*)d_out;

    const int TB = 256;
    int gridN = (N_NODES + TB - 1) / TB;
    int gridE = (ET + TB - 1) / TB;

    // --- dtype probe + CSR by destination (shared by both layers) ---
    probe_kernel<<<1, 256>>>((const int*)ei);
    zero_counts_kernel<<<gridN, TB>>>();
    count_kernel<<<gridE, TB>>>(ei);
    scan_part_kernel<<<NBLK, SCAN_BLK>>>();
    scan_sums_kernel<<<1, 64>>>();
    scan_fixup_kernel<<<NBLK, SCAN_BLK>>>();
    copy_cursor_kernel<<<gridN, TB>>>();
    scatter_kernel<<<gridE, TB>>>(ei);

    // --- layer 1: H=3, C=64 ---
    {
        dim3 g((N_NODES + 127) / 128, (HEADS * HID) / 64);
        sgemm128_kernel<<<g, 256>>>(x, W1, N_NODES, HEADS * HID, D_IN);
    }
    alpha_kernel<<<(N_NODES * HEADS + 7) / 8, 256>>>(as1, ad1, HEADS);
    aggregate_kernel<HEADS, HID><<<N_NODES, HEADS * HID>>>(b1, nullptr);

    // --- layer 2: H=1, C=64 (g_xw reused) ---
    {
        dim3 g((N_NODES + 127) / 128, HID / 64);
        sgemm128_kernel<<<g, 256>>>(nullptr, W2, N_NODES, HID, HEADS * HID);
    }
    alpha_kernel<<<(N_NODES + 7) / 8, 256>>>(as2, ad2, 1);
    aggregate_kernel<1, HID><<<N_NODES, HID>>>(b2, out);
}

// round 5
// speedup vs baseline: 1.4210x; 1.2171x over previous
#include <cuda_runtime.h>
#include <cstdint>
#include <cstddef>

#define N_NODES 50000
#define NE      640000
#define ET      (NE + N_NODES)   // edges + self loops = 690000
#define D_IN    128
#define HID     64
#define HEADS   3
#define SLOPE   0.2f
#define EPS     1e-16f

#define SCAN_BLK 1024
#define NBLK     ((N_NODES + SCAN_BLK - 1) / SCAN_BLK)   // 49

// ---------------- scratch (no allocations; referenced ONLY from device code) ----------------
__device__ float g_xw[(size_t)N_NODES * HEADS * HID];   // xw1 then reused as xw2
__device__ float g_h1[(size_t)N_NODES * HEADS * HID];   // layer-1 output
__device__ float g_asrc[N_NODES * HEADS];
__device__ float g_adst[N_NODES * HEADS];
__device__ int   g_counts[N_NODES];
__device__ int   g_offsets[N_NODES + 1];
__device__ int   g_cursor[N_NODES];
__device__ int   g_csr_src[ET];
__device__ int   g_blocksums[NBLK];
__device__ int   g_blockbase[NBLK];
__device__ int   g_is64;

// ---------------- edge-index dtype probe ----------------
// int64 (<2^31, LE): every odd 32-bit word is 0. int32: odd words are random ids.
__global__ void probe_kernel(const int* __restrict__ ei32) {
    __shared__ int s_or[256];
    int tid = threadIdx.x;
    int acc = 0;
    for (int i = tid; i < 2048; i += 256) acc |= ei32[2 * i + 1];
    s_or[tid] = acc;
    __syncthreads();
    for (int s = 128; s > 0; s >>= 1) {
        if (tid < s) s_or[tid] |= s_or[tid + s];
        __syncthreads();
    }
    if (tid == 0) g_is64 = (s_or[0] == 0) ? 1 : 0;
}

__device__ __forceinline__ int edge_at(const void* ei, long long idx) {
    if (g_is64) return (int)((const long long*)ei)[idx];
    return ((const int*)ei)[idx];
}

// ---------------- CSR build ----------------
__global__ void zero_counts_kernel() {
    int i = blockIdx.x * blockDim.x + threadIdx.x;
    if (i < N_NODES) g_counts[i] = 0;
}

__global__ void count_kernel(const void* __restrict__ ei) {
    int e = blockIdx.x * blockDim.x + threadIdx.x;
    if (e >= ET) return;
    int dst = (e < NE) ? edge_at(ei, (long long)NE + e) : (e - NE);
    atomicAdd(&g_counts[dst], 1);
}

// multi-block scan, stage 1: per-block exclusive scan + block total
__global__ void scan_part_kernel() {
    __shared__ int warp_sums[32];
    int tid = threadIdx.x, lane = tid & 31, wid = tid >> 5;
    int idx = blockIdx.x * SCAN_BLK + tid;
    int v = (idx < N_NODES) ? g_counts[idx] : 0;
    int x = v;
    #pragma unroll
    for (int o = 1; o < 32; o <<= 1) {
        int y = __shfl_up_sync(0xffffffffu, x, o);
        if (lane >= o) x += y;
    }
    if (lane == 31) warp_sums[wid] = x;
    __syncthreads();
    if (wid == 0) {
        int w = warp_sums[lane];
        #pragma unroll
        for (int o = 1; o < 32; o <<= 1) {
            int y = __shfl_up_sync(0xffffffffu, w, o);
            if (lane >= o) w += y;
        }
        warp_sums[lane] = w;
    }
    __syncthreads();
    int warp_off = (wid > 0) ? warp_sums[wid - 1] : 0;
    int incl = x + warp_off;
    if (idx < N_NODES) g_offsets[idx] = incl - v;   // local exclusive
    if (tid == SCAN_BLK - 1) g_blocksums[blockIdx.x] = incl;
}

// stage 2: scan NBLK block sums
__global__ void scan_sums_kernel() {
    int tid = threadIdx.x;                 // 64 threads
    __shared__ int s[NBLK];
    if (tid < NBLK) s[tid] = g_blocksums[tid];
    __syncthreads();
    if (tid == 0) {
        int run = 0;
        for (int i = 0; i < NBLK; i++) { g_blockbase[i] = run; run += s[i]; }
        g_offsets[N_NODES] = run;
    }
}

// stage 3: add block bases; also init cursor
__global__ void scan_fixup_kernel() {
    int idx = blockIdx.x * SCAN_BLK + threadIdx.x;
    if (idx < N_NODES) {
        int v = g_offsets[idx] + g_blockbase[blockIdx.x];
        g_offsets[idx] = v;
        g_cursor[idx] = v;
    }
}

__global__ void scatter_kernel(const void* __restrict__ ei) {
    int e = blockIdx.x * blockDim.x + threadIdx.x;
    if (e >= ET) return;
    int src, dst;
    if (e < NE) {
        src = edge_at(ei, e);
        dst = edge_at(ei, (long long)NE + e);
    } else {
        src = e - NE; dst = e - NE;
    }
    int pos = atomicAdd(&g_cursor[dst], 1);
    g_csr_src[pos] = src;
}

// ---------------- tf32 tensor-core GEMM: g_xw[M,N] = A[M,K] @ B[K,N] ----------------
// BM=128, BN=64, BK=32; 256 threads = 8 warps in 4(m) x 2(n); 32x32 per warp
// via 2x4 m16n8k8 tf32 mma atoms. K % 32 == 0, N % 64 == 0.
// A_in == nullptr means A = g_h1 (layer 2).
__device__ __forceinline__ float tf32r(float x) {
    uint32_t u;
    asm("cvt.rna.tf32.f32 %0, %1;" : "=r"(u) : "f"(x));
    return __uint_as_float(u);
}

__device__ __forceinline__ void mma_tf32(float* d, const uint32_t* a, const uint32_t* b) {
    asm volatile(
        "mma.sync.aligned.m16n8k8.row.col.f32.tf32.tf32.f32 "
        "{%0,%1,%2,%3}, {%4,%5,%6,%7}, {%8,%9}, {%0,%1,%2,%3};\n"
        : "+f"(d[0]), "+f"(d[1]), "+f"(d[2]), "+f"(d[3])
        : "r"(a[0]), "r"(a[1]), "r"(a[2]), "r"(a[3]), "r"(b[0]), "r"(b[1]));
}

__global__ __launch_bounds__(256)
void gemm_tf32_kernel(const float* __restrict__ A_in, const float* __restrict__ B,
                      int M, int N, int K) {
    const float* A = A_in ? A_in : (const float*)g_h1;
    __shared__ float As[128][36];   // padded (bank spread + 16B-aligned rows)
    __shared__ float Bs[32][68];
    int tid = threadIdx.x;
    int lane = tid & 31, wid = tid >> 5;
    int warp_m = wid & 3, warp_n = wid >> 2;
    int m0 = blockIdx.x * 128, n0 = blockIdx.y * 64;
    int g = lane >> 2, t = lane & 3;

    float acc[2][4][4];
    #pragma unroll
    for (int i = 0; i < 2; i++)
        #pragma unroll
        for (int j = 0; j < 4; j++)
            #pragma unroll
            for (int q = 0; q < 4; q++) acc[i][j][q] = 0.f;

    for (int k0 = 0; k0 < K; k0 += 32) {
        // stage A: 128x32 floats = 1024 float4 slots, cvt to tf32 once here
        #pragma unroll
        for (int s = tid; s < 1024; s += 256) {
            int r = s >> 3, c = (s & 7) * 4;
            float4 v = make_float4(0.f, 0.f, 0.f, 0.f);
            if (m0 + r < M)
                v = *(const float4*)(A + (size_t)(m0 + r) * K + k0 + c);
            float4 w = make_float4(tf32r(v.x), tf32r(v.y), tf32r(v.z), tf32r(v.w));
            *(float4*)&As[r][c] = w;
        }
        // stage B: 32x64 floats = 512 float4 slots
        #pragma unroll
        for (int s = tid; s < 512; s += 256) {
            int r = s >> 4, c = (s & 15) * 4;
            float4 v = *(const float4*)(B + (size_t)(k0 + r) * N + n0 + c);
            float4 w = make_float4(tf32r(v.x), tf32r(v.y), tf32r(v.z), tf32r(v.w));
            *(float4*)&Bs[r][c] = w;
        }
        __syncthreads();
        #pragma unroll
        for (int k8 = 0; k8 < 32; k8 += 8) {
            uint32_t afr[2][4];
            #pragma unroll
            for (int am = 0; am < 2; am++) {
                int r0 = warp_m * 32 + am * 16 + g;
                afr[am][0] = __float_as_uint(As[r0][k8 + t]);
                afr[am][1] = __float_as_uint(As[r0 + 8][k8 + t]);
                afr[am][2] = __float_as_uint(As[r0][k8 + t + 4]);
                afr[am][3] = __float_as_uint(As[r0 + 8][k8 + t + 4]);
            }
            uint32_t bfr[4][2];
            #pragma unroll
            for (int an = 0; an < 4; an++) {
                int n = warp_n * 32 + an * 8 + g;
                bfr[an][0] = __float_as_uint(Bs[k8 + t][n]);
                bfr[an][1] = __float_as_uint(Bs[k8 + t + 4][n]);
            }
            #pragma unroll
            for (int am = 0; am < 2; am++)
                #pragma unroll
                for (int an = 0; an < 4; an++)
                    mma_tf32(acc[am][an], afr[am], bfr[an]);
        }
        __syncthreads();
    }

    // store C
    #pragma unroll
    for (int am = 0; am < 2; am++) {
        int r0 = m0 + warp_m * 32 + am * 16 + g;
        #pragma unroll
        for (int an = 0; an < 4; an++) {
            int cn = n0 + warp_n * 32 + an * 8 + 2 * t;
            if (r0 < M)
                *(float2*)&g_xw[(size_t)r0 * N + cn] =
                    make_float2(acc[am][an][0], acc[am][an][1]);
            if (r0 + 8 < M)
                *(float2*)&g_xw[(size_t)(r0 + 8) * N + cn] =
                    make_float2(acc[am][an][2], acc[am][an][3]);
        }
    }
}

// ---------------- per-node attention coefficients (a_src, a_dst dots) ----------------
__global__ void alpha_kernel(const float* __restrict__ a_src,
                             const float* __restrict__ a_dst, int H) {
    int warp = (blockIdx.x * blockDim.x + threadIdx.x) >> 5;
    int lane = threadIdx.x & 31;
    if (warp >= N_NODES * H) return;
    int n = warp / H, h = warp % H;
    const float* row = g_xw + (size_t)n * H * HID + h * HID;
    const float* asv = a_src + h * HID;
    const float* adv = a_dst + h * HID;
    float s1 = row[lane] * asv[lane] + row[lane + 32] * asv[lane + 32];
    float s2 = row[lane] * adv[lane] + row[lane + 32] * adv[lane + 32];
    #pragma unroll
    for (int o = 16; o > 0; o >>= 1) {
        s1 += __shfl_xor_sync(0xffffffffu, s1, o);
        s2 += __shfl_xor_sync(0xffffffffu, s2, o);
    }
    if (lane == 0) {
        g_asrc[n * H + h] = s1;
        g_adst[n * H + h] = s2;
    }
}

// ---------------- fused per-node softmax + aggregation ----------------
// out[n] = relu(sum_e ex_e * xw[src_e] / sum_e ex_e + bias)
// ex in-kernel: exp(leaky_relu(asrc[src] + adst[n])); max-subtraction skipped
// (mathematically identical; logits bounded, no overflow).
template <int H, int C>
__global__ void aggregate_kernel(const float* __restrict__ bias,
                                 float* __restrict__ out_p) {
    constexpr int CHUNK = 64;
    float* out = out_p ? out_p : (float*)g_h1;
    int n = blockIdx.x;
    int tid = threadIdx.x;            // H*C threads (192 or 64)
    int h = tid / C;
    int c = tid % C;
    int beg = g_offsets[n], end = g_offsets[n + 1];
    __shared__ int   s_src[CHUNK];
    __shared__ float s_ex[CHUNK * H];
    float acc = 0.f, denom = 0.f;
    for (int base = beg; base < end; base += CHUNK) {
        int ne = min(CHUNK, end - base);
        __syncthreads();
        if (tid < ne) s_src[tid] = g_csr_src[base + tid];
        __syncthreads();
        if (tid < ne * H) {
            int j = tid / H, hh = tid % H;
            float v = g_asrc[s_src[j] * H + hh] + g_adst[n * H + hh];
            v = (v > 0.f) ? v : SLOPE * v;
            s_ex[tid] = __expf(v);
        }
        __syncthreads();
        for (int j = 0; j < ne; j++) {
            float e = s_ex[j * H + h];
            denom += e;
            acc += e * g_xw[(size_t)s_src[j] * (H * C) + h * C + c];
        }
    }
    float r = acc / (denom + EPS) + bias[tid];
    out[(size_t)n * (H * C) + tid] = fmaxf(r, 0.f);
}

// ---------------- launch ----------------
extern "C" void kernel_launch(void* const* d_in, const int* in_sizes, int n_in,
                              void* d_out, int out_size) {
    const float* x   = (const float*)d_in[0];
    const void*  ei  = d_in[1];                 // int32 or int64 (probed on device)
    const float* W1  = (const float*)d_in[2];
    const float* as1 = (const float*)d_in[3];
    const float* ad1 = (const float*)d_in[4];
    const float* b1  = (const float*)d_in[5];
    const float* W2  = (const float*)d_in[6];
    const float* as2 = (const float*)d_in[7];
    const float* ad2 = (const float*)d_in[8];
    const float* b2  = (const float*)d_in[9];
    float*       out = (float*)d_out;

    const int TB = 256;
    int gridN = (N_NODES + TB - 1) / TB;
    int gridE = (ET + TB - 1) / TB;

    // launches 1-3: probe + counts
    probe_kernel<<<1, 256>>>((const int*)ei);
    zero_counts_kernel<<<gridN, TB>>>();
    count_kernel<<<gridE, TB>>>(ei);

    // launch 4: GEMM1 (independent of CSR; placed here so ncu profiles it)
    {
        dim3 g((N_NODES + 127) / 128, (HEADS * HID) / 64);
        gemm_tf32_kernel<<<g, 256>>>(x, W1, N_NODES, HEADS * HID, D_IN);
    }

    // CSR finish
    scan_part_kernel<<<NBLK, SCAN_BLK>>>();
    scan_sums_kernel<<<1, 64>>>();
    scan_fixup_kernel<<<NBLK, SCAN_BLK>>>();
    scatter_kernel<<<gridE, TB>>>(ei);

    // layer 1 attention + aggregate
    alpha_kernel<<<(N_NODES * HEADS + 7) / 8, 256>>>(as1, ad1, HEADS);
    aggregate_kernel<HEADS, HID><<<N_NODES, HEADS * HID>>>(b1, nullptr);

    // layer 2
    {
        dim3 g((N_NODES + 127) / 128, HID / 64);
        gemm_tf32_kernel<<<g, 256>>>(nullptr, W2, N_NODES, HID, HEADS * HID);
    }
    alpha_kernel<<<(N_NODES + 7) / 8, 256>>>(as2, ad2, 1);
    aggregate_kernel<1, HID><<<N_NODES, HID>>>(b2, out);
}

// round 6
// speedup vs baseline: 1.7497x; 1.2313x over previous
#include <cuda_runtime.h>
#include <cuda_fp16.h>
#include <cstdint>
#include <cstddef>

#define N_NODES 50000
#define NE      640000
#define ET      (NE + N_NODES)   // edges + self loops = 690000
#define D_IN    128
#define HID     64
#define HEADS   3
#define SLOPE   0.2f
#define EPS     1e-16f

#define SCAN_BLK 1024
#define NBLK     ((N_NODES + SCAN_BLK - 1) / SCAN_BLK)   // 49

// ---------------- scratch (no allocations; referenced ONLY from device code) ----------------
__device__ __half g_xwh[(size_t)N_NODES * HEADS * HID]; // fp16 features (xw1, then xw2)
__device__ float  g_h1[(size_t)N_NODES * HEADS * HID];  // layer-1 output (fp32, GEMM2 input)
__device__ float  g_asrc[N_NODES * HEADS];
__device__ float  g_adst[N_NODES * HEADS];
__device__ int    g_counts[N_NODES];
__device__ int    g_offsets[N_NODES + 1];
__device__ int    g_cursor[N_NODES];
__device__ int    g_csr_src[ET];
__device__ int    g_blocksums[NBLK];
__device__ int    g_blockbase[NBLK];
__device__ int    g_is64;

// ---------------- edge-index dtype probe ----------------
// int64 (<2^31, LE): every odd 32-bit word is 0. int32: odd words are random ids.
__global__ void probe_kernel(const int* __restrict__ ei32) {
    __shared__ int s_or[256];
    int tid = threadIdx.x;
    int acc = 0;
    for (int i = tid; i < 2048; i += 256) acc |= ei32[2 * i + 1];
    s_or[tid] = acc;
    __syncthreads();
    for (int s = 128; s > 0; s >>= 1) {
        if (tid < s) s_or[tid] |= s_or[tid + s];
        __syncthreads();
    }
    if (tid == 0) g_is64 = (s_or[0] == 0) ? 1 : 0;
}

__device__ __forceinline__ int edge_at(const void* ei, long long idx) {
    if (g_is64) return (int)((const long long*)ei)[idx];
    return ((const int*)ei)[idx];
}

// ---------------- CSR build ----------------
__global__ void zero_counts_kernel() {
    int i = blockIdx.x * blockDim.x + threadIdx.x;
    if (i < N_NODES) g_counts[i] = 0;
}

__global__ void count_kernel(const void* __restrict__ ei) {
    int e = blockIdx.x * blockDim.x + threadIdx.x;
    if (e >= ET) return;
    int dst = (e < NE) ? edge_at(ei, (long long)NE + e) : (e - NE);
    atomicAdd(&g_counts[dst], 1);
}

__global__ void scan_part_kernel() {
    __shared__ int warp_sums[32];
    int tid = threadIdx.x, lane = tid & 31, wid = tid >> 5;
    int idx = blockIdx.x * SCAN_BLK + tid;
    int v = (idx < N_NODES) ? g_counts[idx] : 0;
    int x = v;
    #pragma unroll
    for (int o = 1; o < 32; o <<= 1) {
        int y = __shfl_up_sync(0xffffffffu, x, o);
        if (lane >= o) x += y;
    }
    if (lane == 31) warp_sums[wid] = x;
    __syncthreads();
    if (wid == 0) {
        int w = warp_sums[lane];
        #pragma unroll
        for (int o = 1; o < 32; o <<= 1) {
            int y = __shfl_up_sync(0xffffffffu, w, o);
            if (lane >= o) w += y;
        }
        warp_sums[lane] = w;
    }
    __syncthreads();
    int warp_off = (wid > 0) ? warp_sums[wid - 1] : 0;
    int incl = x + warp_off;
    if (idx < N_NODES) g_offsets[idx] = incl - v;   // local exclusive
    if (tid == SCAN_BLK - 1) g_blocksums[blockIdx.x] = incl;
}

__global__ void scan_sums_kernel() {
    int tid = threadIdx.x;                 // 64 threads
    __shared__ int s[NBLK];
    if (tid < NBLK) s[tid] = g_blocksums[tid];
    __syncthreads();
    if (tid == 0) {
        int run = 0;
        for (int i = 0; i < NBLK; i++) { g_blockbase[i] = run; run += s[i]; }
        g_offsets[N_NODES] = run;
    }
}

__global__ void scan_fixup_kernel() {
    int idx = blockIdx.x * SCAN_BLK + threadIdx.x;
    if (idx < N_NODES) {
        int v = g_offsets[idx] + g_blockbase[blockIdx.x];
        g_offsets[idx] = v;
        g_cursor[idx] = v;
    }
}

__global__ void scatter_kernel(const void* __restrict__ ei) {
    int e = blockIdx.x * blockDim.x + threadIdx.x;
    if (e >= ET) return;
    int src, dst;
    if (e < NE) {
        src = edge_at(ei, e);
        dst = edge_at(ei, (long long)NE + e);
    } else {
        src = e - NE; dst = e - NE;
    }
    int pos = atomicAdd(&g_cursor[dst], 1);
    g_csr_src[pos] = src;
}

// ---------------- tf32 tensor-core GEMM -> fp16 feature buffer ----------------
// g_xwh[M,N] = half(A[M,K] @ B[K,N]).  BM=128, BN=64, BK=32; 8 warps 4x2;
// 32x32 per warp via 2x4 m16n8k8 tf32 atoms. A_in == nullptr -> A = g_h1.
__device__ __forceinline__ float tf32r(float x) {
    uint32_t u;
    asm("cvt.rna.tf32.f32 %0, %1;" : "=r"(u) : "f"(x));
    return __uint_as_float(u);
}

__device__ __forceinline__ void mma_tf32(float* d, const uint32_t* a, const uint32_t* b) {
    asm volatile(
        "mma.sync.aligned.m16n8k8.row.col.f32.tf32.tf32.f32 "
        "{%0,%1,%2,%3}, {%4,%5,%6,%7}, {%8,%9}, {%0,%1,%2,%3};\n"
        : "+f"(d[0]), "+f"(d[1]), "+f"(d[2]), "+f"(d[3])
        : "r"(a[0]), "r"(a[1]), "r"(a[2]), "r"(a[3]), "r"(b[0]), "r"(b[1]));
}

__global__ __launch_bounds__(256)
void gemm_tf32_kernel(const float* __restrict__ A_in, const float* __restrict__ B,
                      int M, int N, int K) {
    const float* A = A_in ? A_in : (const float*)g_h1;
    __shared__ float As[128][36];
    __shared__ float Bs[32][68];
    int tid = threadIdx.x;
    int lane = tid & 31, wid = tid >> 5;
    int warp_m = wid & 3, warp_n = wid >> 2;
    int m0 = blockIdx.x * 128, n0 = blockIdx.y * 64;
    int g = lane >> 2, t = lane & 3;

    float acc[2][4][4];
    #pragma unroll
    for (int i = 0; i < 2; i++)
        #pragma unroll
        for (int j = 0; j < 4; j++)
            #pragma unroll
            for (int q = 0; q < 4; q++) acc[i][j][q] = 0.f;

    for (int k0 = 0; k0 < K; k0 += 32) {
        #pragma unroll
        for (int s = tid; s < 1024; s += 256) {
            int r = s >> 3, c = (s & 7) * 4;
            float4 v = make_float4(0.f, 0.f, 0.f, 0.f);
            if (m0 + r < M)
                v = *(const float4*)(A + (size_t)(m0 + r) * K + k0 + c);
            float4 w = make_float4(tf32r(v.x), tf32r(v.y), tf32r(v.z), tf32r(v.w));
            *(float4*)&As[r][c] = w;
        }
        #pragma unroll
        for (int s = tid; s < 512; s += 256) {
            int r = s >> 4, c = (s & 15) * 4;
            float4 v = *(const float4*)(B + (size_t)(k0 + r) * N + n0 + c);
            float4 w = make_float4(tf32r(v.x), tf32r(v.y), tf32r(v.z), tf32r(v.w));
            *(float4*)&Bs[r][c] = w;
        }
        __syncthreads();
        #pragma unroll
        for (int k8 = 0; k8 < 32; k8 += 8) {
            uint32_t afr[2][4];
            #pragma unroll
            for (int am = 0; am < 2; am++) {
                int r0 = warp_m * 32 + am * 16 + g;
                afr[am][0] = __float_as_uint(As[r0][k8 + t]);
                afr[am][1] = __float_as_uint(As[r0 + 8][k8 + t]);
                afr[am][2] = __float_as_uint(As[r0][k8 + t + 4]);
                afr[am][3] = __float_as_uint(As[r0 + 8][k8 + t + 4]);
            }
            uint32_t bfr[4][2];
            #pragma unroll
            for (int an = 0; an < 4; an++) {
                int n = warp_n * 32 + an * 8 + g;
                bfr[an][0] = __float_as_uint(Bs[k8 + t][n]);
                bfr[an][1] = __float_as_uint(Bs[k8 + t + 4][n]);
            }
            #pragma unroll
            for (int am = 0; am < 2; am++)
                #pragma unroll
                for (int an = 0; an < 4; an++)
                    mma_tf32(acc[am][an], afr[am], bfr[an]);
        }
        __syncthreads();
    }

    // store C as fp16
    #pragma unroll
    for (int am = 0; am < 2; am++) {
        int r0 = m0 + warp_m * 32 + am * 16 + g;
        #pragma unroll
        for (int an = 0; an < 4; an++) {
            int cn = n0 + warp_n * 32 + an * 8 + 2 * t;
            if (r0 < M)
                *(__half2*)&g_xwh[(size_t)r0 * N + cn] =
                    __floats2half2_rn(acc[am][an][0], acc[am][an][1]);
            if (r0 + 8 < M)
                *(__half2*)&g_xwh[(size_t)(r0 + 8) * N + cn] =
                    __floats2half2_rn(acc[am][an][2], acc[am][an][3]);
        }
    }
}

// ---------------- per-node attention coefficients (reads fp16 features) ----------------
__global__ void alpha_kernel(const float* __restrict__ a_src,
                             const float* __restrict__ a_dst, int H) {
    int warp = (blockIdx.x * blockDim.x + threadIdx.x) >> 5;
    int lane = threadIdx.x & 31;
    if (warp >= N_NODES * H) return;
    int n = warp / H, h = warp % H;
    const __half* row = g_xwh + (size_t)n * H * HID + h * HID;
    const float* asv = a_src + h * HID;
    const float* adv = a_dst + h * HID;
    float r1 = __half2float(row[lane]);
    float r2 = __half2float(row[lane + 32]);
    float s1 = r1 * asv[lane] + r2 * asv[lane + 32];
    float s2 = r1 * adv[lane] + r2 * adv[lane + 32];
    #pragma unroll
    for (int o = 16; o > 0; o >>= 1) {
        s1 += __shfl_xor_sync(0xffffffffu, s1, o);
        s2 += __shfl_xor_sync(0xffffffffu, s2, o);
    }
    if (lane == 0) {
        g_asrc[n * H + h] = s1;
        g_adst[n * H + h] = s2;
    }
}

// ---------------- warp-centric fused softmax + aggregation ----------------
// One warp per (node, head). Lane j computes exp for edge j (coalesced);
// shfl-broadcast inner loop gathers half2 features with unroll-4 MLP.
// Max-subtraction skipped (identical result; logits bounded).
// out_p == nullptr -> write g_h1 (layer 1).
template <int H, int C>
__global__ __launch_bounds__(256)
void aggregate_warp_kernel(const float* __restrict__ bias,
                           float* __restrict__ out_p) {
    float* out = out_p ? out_p : (float*)g_h1;
    int gw = (blockIdx.x * blockDim.x + threadIdx.x) >> 5;
    int lane = threadIdx.x & 31;
    if (gw >= N_NODES * H) return;
    int n = gw / H, h = gw % H;
    int beg = g_offsets[n], end = g_offsets[n + 1];
    float adst_n = g_adst[n * H + h];

    float2 acc = make_float2(0.f, 0.f);
    float denom = 0.f;
    const __half* xwh = g_xwh;

    for (int base = beg; base < end; base += 32) {
        int j = base + lane;
        bool valid = j < end;
        int s = valid ? g_csr_src[j] : 0;
        float e = 0.f;
        if (valid) {
            float v = g_asrc[s * H + h] + adst_n;
            v = (v > 0.f) ? v : SLOPE * v;
            e = __expf(v);
        }
        denom += e;
        int ne = min(32, end - base);
        int jj = 0;
        for (; jj + 4 <= ne; jj += 4) {
            float e0 = __shfl_sync(0xffffffffu, e, jj + 0);
            float e1 = __shfl_sync(0xffffffffu, e, jj + 1);
            float e2 = __shfl_sync(0xffffffffu, e, jj + 2);
            float e3 = __shfl_sync(0xffffffffu, e, jj + 3);
            int   s0 = __shfl_sync(0xffffffffu, s, jj + 0);
            int   s1 = __shfl_sync(0xffffffffu, s, jj + 1);
            int   s2 = __shfl_sync(0xffffffffu, s, jj + 2);
            int   s3 = __shfl_sync(0xffffffffu, s, jj + 3);
            float2 f0 = __half22float2(*(const __half2*)&xwh[(size_t)s0 * (H * C) + h * C + 2 * lane]);
            float2 f1 = __half22float2(*(const __half2*)&xwh[(size_t)s1 * (H * C) + h * C + 2 * lane]);
            float2 f2 = __half22float2(*(const __half2*)&xwh[(size_t)s2 * (H * C) + h * C + 2 * lane]);
            float2 f3 = __half22float2(*(const __half2*)&xwh[(size_t)s3 * (H * C) + h * C + 2 * lane]);
            acc.x += e0 * f0.x; acc.y += e0 * f0.y;
            acc.x += e1 * f1.x; acc.y += e1 * f1.y;
            acc.x += e2 * f2.x; acc.y += e2 * f2.y;
            acc.x += e3 * f3.x; acc.y += e3 * f3.y;
        }
        for (; jj < ne; jj++) {
            float ee = __shfl_sync(0xffffffffu, e, jj);
            int   ss = __shfl_sync(0xffffffffu, s, jj);
            float2 f = __half22float2(*(const __half2*)&xwh[(size_t)ss * (H * C) + h * C + 2 * lane]);
            acc.x += ee * f.x; acc.y += ee * f.y;
        }
    }
    #pragma unroll
    for (int o = 16; o > 0; o >>= 1)
        denom += __shfl_xor_sync(0xffffffffu, denom, o);
    float inv = 1.f / (denom + EPS);
    int c0 = h * C + 2 * lane;
    float2 r = make_float2(fmaxf(acc.x * inv + bias[c0], 0.f),
                           fmaxf(acc.y * inv + bias[c0 + 1], 0.f));
    *(float2*)&out[(size_t)n * (H * C) + c0] = r;
}

// ---------------- launch ----------------
extern "C" void kernel_launch(void* const* d_in, const int* in_sizes, int n_in,
                              void* d_out, int out_size) {
    const float* x   = (const float*)d_in[0];
    const void*  ei  = d_in[1];                 // int32 or int64 (probed on device)
    const float* W1  = (const float*)d_in[2];
    const float* as1 = (const float*)d_in[3];
    const float* ad1 = (const float*)d_in[4];
    const float* b1  = (const float*)d_in[5];
    const float* W2  = (const float*)d_in[6];
    const float* as2 = (const float*)d_in[7];
    const float* ad2 = (const float*)d_in[8];
    const float* b2  = (const float*)d_in[9];
    float*       out = (float*)d_out;

    const int TB = 256;
    int gridN = (N_NODES + TB - 1) / TB;
    int gridE = (ET + TB - 1) / TB;

    probe_kernel<<<1, 256>>>((const int*)ei);
    zero_counts_kernel<<<gridN, TB>>>();
    count_kernel<<<gridE, TB>>>(ei);

    // launch 4: GEMM1 (profiled slot)
    {
        dim3 g((N_NODES + 127) / 128, (HEADS * HID) / 64);
        gemm_tf32_kernel<<<g, 256>>>(x, W1, N_NODES, HEADS * HID, D_IN);
    }

    scan_part_kernel<<<NBLK, SCAN_BLK>>>();
    scan_sums_kernel<<<1, 64>>>();
    scan_fixup_kernel<<<NBLK, SCAN_BLK>>>();
    scatter_kernel<<<gridE, TB>>>(ei);

    alpha_kernel<<<(N_NODES * HEADS + 7) / 8, 256>>>(as1, ad1, HEADS);
    aggregate_warp_kernel<HEADS, HID>
        <<<(N_NODES * HEADS + 7) / 8, 256>>>(b1, nullptr);

    {
        dim3 g((N_NODES + 127) / 128, HID / 64);
        gemm_tf32_kernel<<<g, 256>>>(nullptr, W2, N_NODES, HID, HEADS * HID);
    }
    alpha_kernel<<<(N_NODES + 7) / 8, 256>>>(as2, ad2, 1);
    aggregate_warp_kernel<1, HID>
        <<<(N_NODES + 7) / 8, 256>>>(b2, out);
}